// round 8
// baseline (speedup 1.0000x reference)
#include <cuda_runtime.h>
#include <cstdint>
#include <math.h>

#define NC 16       // components
#define NDIM 16     // dimension
#define NL 6        // flow steps

// ---------------------------------------------------------------------------
// Device globals (setup kernel -> main kernel). No dynamic allocation.
// ---------------------------------------------------------------------------
__device__ float g_P[NC * NDIM * NDIM];    // L^{-1} per component (zeros above diag)
__device__ float g_base[NC];               // -0.5*DIM*log(2pi) - half_logdet
__device__ float2 g_ab[NL * NC];           // (exp(log_alpha), beta) packed
__device__ float g_e[NC * NL * NDIM];      // [c][l][i]: l<5: z0_l - z0_{l+1}; l=5: z0_5
__device__ float g_nz00[NC * NDIM];        // -z0_0
__device__ int   g_flag;                   // 1 if P==I for all c and mean==0

// ---------------------------------------------------------------------------
// Packed f32x2 helpers on raw 64-bit pairs.
// ---------------------------------------------------------------------------
typedef unsigned long long u64;

__device__ __forceinline__ u64 add2(u64 a, u64 b) {
    u64 r; asm("add.rn.f32x2 %0, %1, %2;" : "=l"(r) : "l"(a), "l"(b)); return r;
}
__device__ __forceinline__ u64 mul2(u64 a, u64 b) {
    u64 r; asm("mul.rn.f32x2 %0, %1, %2;" : "=l"(r) : "l"(a), "l"(b)); return r;
}
__device__ __forceinline__ u64 fma2(u64 a, u64 b, u64 c) {
    u64 r; asm("fma.rn.f32x2 %0, %1, %2, %3;" : "=l"(r) : "l"(a), "l"(b), "l"(c)); return r;
}
__device__ __forceinline__ u64 bcast2(float x) {
    u64 r; asm("mov.b64 %0, {%1, %1};" : "=l"(r) : "f"(x)); return r;
}
__device__ __forceinline__ float hsum2(u64 a) {
    float x, y; asm("mov.b64 {%0, %1}, %2;" : "=f"(x), "=f"(y) : "l"(a));
    return x + y;
}

// ---------------------------------------------------------------------------
// Setup: Cholesky -> P = L^{-1}, base, (alpha,beta) pack, flow deltas e,
// and the fast-path flag (P exactly identity AND mean exactly zero).
// One block, (16,16): x = row/element i, y = component c.
// ---------------------------------------------------------------------------
__global__ void setup_kernel(const float* __restrict__ log_alpha,
                             const float* __restrict__ beta_g,
                             const float* __restrict__ cov,
                             const float* __restrict__ z0,
                             const float* __restrict__ mean) {
    const int i = threadIdx.x;   // row / element
    const int c = threadIdx.y;   // component

    __shared__ float scol[NC][NDIM];
    __shared__ float sL[NC][NDIM][NDIM];

    float a[NDIM];
#pragma unroll
    for (int j = 0; j < NDIM; j++) a[j] = cov[(c * NDIM + i) * NDIM + j];

    float Lrow[NDIM];
#pragma unroll
    for (int k = 0; k < NDIM; k++) {
        if (i == k) scol[c][k] = sqrtf(a[k]);
        __syncthreads();
        float lkk = scol[c][k];
        if (i > k) scol[c][i] = a[k] / lkk;
        __syncthreads();
        float lik = (i >= k) ? scol[c][i] : 0.0f;
        Lrow[k] = lik;
        float upd = (i > k) ? lik : 0.0f;
#pragma unroll
        for (int j = 0; j < NDIM; j++) {
            if (j > k) a[j] -= upd * scol[c][j];
        }
        __syncthreads();
    }
#pragma unroll
    for (int k = 0; k < NDIM; k++) sL[c][i][k] = Lrow[k];
    __syncthreads();

    // Thread i computes column i of P = L^{-1} (forward substitution on e_i).
    bool ok = true;
    {
        float x[NDIM];
#pragma unroll
        for (int r = 0; r < NDIM; r++) {
            float s = (r == i) ? 1.0f : 0.0f;
#pragma unroll
            for (int m = 0; m < NDIM; m++) {
                if (m < r) s -= sL[c][r][m] * x[m];
            }
            x[r] = s / sL[c][r][r];
            g_P[(c * NDIM + r) * NDIM + i] = x[r];
            ok = ok && (x[r] == ((r == i) ? 1.0f : 0.0f));
        }
    }
    ok = ok && (mean[c * NDIM + i] == 0.0f);

    if (i == 0) {
        float hld = 0.0f;
#pragma unroll
        for (int d = 0; d < NDIM; d++) hld += logf(sL[c][d][d]);
        g_base[c] = -8.0f * 1.83787706640934548356f - hld;
    }

    // Flow precompute: e[c][l][i]
#pragma unroll
    for (int l = 0; l < NL - 1; l++) {
        g_e[c * (NL * NDIM) + l * NDIM + i] =
            z0[(l * NC + c) * NDIM + i] - z0[((l + 1) * NC + c) * NDIM + i];
    }
    g_e[c * (NL * NDIM) + (NL - 1) * NDIM + i] = z0[((NL - 1) * NC + c) * NDIM + i];
    g_nz00[c * NDIM + i] = -z0[(0 * NC + c) * NDIM + i];

    int t = c * NDIM + i;
    if (t < NL * NC) g_ab[t] = make_float2(expf(log_alpha[t]), beta_g[t]);

    int all = __syncthreads_and(ok ? 1 : 0);
    if (t == 0) g_flag = all;
}

// ---------------------------------------------------------------------------
// General path for one point (arbitrary cov/mean). Correctness fallback.
// ---------------------------------------------------------------------------
__device__ float general_one(const float* __restrict__ z, int nn, int c,
                             const float* s_nz0all, const float* s_P,
                             const float* s_nmean, const float2* s_ab,
                             const float* s_base) {
    u64 zc[8];
    {
        const ulonglong2* zp = reinterpret_cast<const ulonglong2*>(z + (size_t)nn * NDIM);
#pragma unroll
        for (int q = 0; q < 4; q++) {
            ulonglong2 a = zp[q];
            zc[q * 2 + 0] = a.x;
            zc[q * 2 + 1] = a.y;
        }
    }
    float slj = 0.0f;
#pragma unroll
    for (int l = 0; l < NL; l++) {
        const ulonglong2* nz2 =
            reinterpret_cast<const ulonglong2*>(&s_nz0all[(l * NC + c) * NDIM]);
        u64 d[8], acc0, acc1;
        {
            ulonglong2 v0 = nz2[0], v1 = nz2[1];
            d[0] = add2(zc[0], v0.x);
            d[1] = add2(zc[1], v0.y);
            d[2] = add2(zc[2], v1.x);
            d[3] = add2(zc[3], v1.y);
            acc0 = mul2(d[0], d[0]);
            acc1 = mul2(d[1], d[1]);
            acc0 = fma2(d[2], d[2], acc0);
            acc1 = fma2(d[3], d[3], acc1);
            ulonglong2 v2 = nz2[2], v3 = nz2[3];
            d[4] = add2(zc[4], v2.x);
            d[5] = add2(zc[5], v2.y);
            d[6] = add2(zc[6], v3.x);
            d[7] = add2(zc[7], v3.y);
            acc0 = fma2(d[4], d[4], acc0);
            acc1 = fma2(d[5], d[5], acc1);
            acc0 = fma2(d[6], d[6], acc0);
            acc1 = fma2(d[7], d[7], acc1);
        }
        float r2 = hsum2(add2(acc0, acc1));
        float r  = r2 * rsqrtf(r2);
        float2 ab = s_ab[l * NC + c];
        float h  = __fdividef(1.0f, ab.x + r);
        float bh = ab.y * h;
        float rh = r * h;
        u64 bb = bcast2(bh);
#pragma unroll
        for (int j = 0; j < 8; j++) zc[j] = fma2(d[j], bb, zc[j]);
        float t1 = 1.0f + bh;
        slj = fmaf(15.0f, __logf(t1), slj) + __logf(fmaf(-bh, rh, t1));
    }
    {
        const ulonglong2* nm2 =
            reinterpret_cast<const ulonglong2*>(&s_nmean[c * NDIM]);
#pragma unroll
        for (int q = 0; q < 4; q++) {
            ulonglong2 m = nm2[q];
            zc[q * 2 + 0] = add2(zc[q * 2 + 0], m.x);
            zc[q * 2 + 1] = add2(zc[q * 2 + 1], m.y);
        }
    }
    float q = 0.0f;
    const ulonglong2* P2 =
        reinterpret_cast<const ulonglong2*>(&s_P[c * NDIM * NDIM]);
#pragma unroll
    for (int i = 0; i < NDIM; i++) {
        const int nq = i / 4 + 1;
        u64 acc;
        {
            ulonglong2 p = P2[i * 4 + 0];
            acc = mul2(p.x, zc[0]);
            acc = fma2(p.y, zc[1], acc);
        }
#pragma unroll
        for (int w = 1; w < 4; w++) {
            if (w < nq) {
                ulonglong2 p = P2[i * 4 + w];
                acc = fma2(p.x, zc[w * 2 + 0], acc);
                acc = fma2(p.y, zc[w * 2 + 1], acc);
            }
        }
        float sol = hsum2(acc);
        q = fmaf(sol, sol, q);
    }
    return fmaf(q, -0.5f, s_base[c]) + slj;
}

// ---------------------------------------------------------------------------
// Main kernel: block = 512 threads = 16 warps; warp w -> component w.
// Each thread processes TWO points (lane, lane+32): amortizes every shared
// broadcast load and address calc across 2x the FMA work, and gives the
// scalar MUFU/log section 2-way ILP.
// ---------------------------------------------------------------------------
__global__ void __launch_bounds__(512, 1)
density_kernel(const float* __restrict__ z,
               const float* __restrict__ z0,
               const float* __restrict__ mean,
               float* __restrict__ out,
               int N)
{
    __shared__ __align__(16) float s_e[NC * NL * NDIM];      // fast-path deltas
    __shared__ __align__(16) float s_nz00[NC * NDIM];        // -z0_0
    __shared__ __align__(16) float s_nz0all[NL * NC * NDIM]; // general path
    __shared__ __align__(16) float s_P[NC * NDIM * NDIM];    // general path
    __shared__ __align__(16) float s_nmean[NC * NDIM];       // general path
    __shared__ float2 s_ab[NL * NC];
    __shared__ float s_base[NC];
    __shared__ float s_res[64 * 17];                         // [point][comp], pitch 17

    const int tid = threadIdx.x;
    const int flag = g_flag;

    for (int t = tid; t < NC * NL * NDIM; t += 512) s_e[t] = g_e[t];
    if (tid < NC * NDIM) s_nz00[tid] = g_nz00[tid];
    if (tid < NL * NC) s_ab[tid] = g_ab[tid];
    if (tid < NC) s_base[tid] = g_base[tid];
    if (!flag) {
        for (int t = tid; t < NL * NC * NDIM; t += 512) s_nz0all[t] = -z0[t];
        for (int t = tid; t < NC * NDIM * NDIM; t += 512) s_P[t] = g_P[t];
        if (tid < NC * NDIM) s_nmean[tid] = -mean[tid];
    }
    __syncthreads();

    const int c    = tid >> 5;          // warp-uniform component
    const int lane = tid & 31;
    const int nA   = blockIdx.x * 64 + lane;
    const int nB   = nA + 32;
    const int nnA  = (nA < N) ? nA : 0;
    const int nnB  = (nB < N) ? nB : 0;

    float vA, vB;

    if (flag) {
        // ================= FAST PATH: cov = I, mean = 0 =================
        u64 dA[8], dB[8];
        {
            const ulonglong2* zpA = reinterpret_cast<const ulonglong2*>(z + (size_t)nnA * NDIM);
            const ulonglong2* zpB = reinterpret_cast<const ulonglong2*>(z + (size_t)nnB * NDIM);
            const ulonglong2* z00 = reinterpret_cast<const ulonglong2*>(&s_nz00[c * NDIM]);
#pragma unroll
            for (int q = 0; q < 4; q++) {
                ulonglong2 a = zpA[q];
                ulonglong2 b = zpB[q];
                ulonglong2 m = z00[q];
                dA[q * 2 + 0] = add2(a.x, m.x);
                dA[q * 2 + 1] = add2(a.y, m.y);
                dB[q * 2 + 0] = add2(b.x, m.x);
                dB[q * 2 + 1] = add2(b.y, m.y);
            }
        }

        const ulonglong2* e2 = reinterpret_cast<const ulonglong2*>(&s_e[c * (NL * NDIM)]);
        float p15A = 1.0f, pgA = 1.0f, p15B = 1.0f, pgB = 1.0f;
#pragma unroll
        for (int l = 0; l < NL; l++) {
            // |d|^2 for both points (independent chains -> ILP)
            u64 a0 = mul2(dA[0], dA[0]);
            u64 a1 = mul2(dA[1], dA[1]);
            u64 b0 = mul2(dB[0], dB[0]);
            u64 b1 = mul2(dB[1], dB[1]);
#pragma unroll
            for (int j = 1; j < 4; j++) {
                a0 = fma2(dA[j * 2 + 0], dA[j * 2 + 0], a0);
                a1 = fma2(dA[j * 2 + 1], dA[j * 2 + 1], a1);
                b0 = fma2(dB[j * 2 + 0], dB[j * 2 + 0], b0);
                b1 = fma2(dB[j * 2 + 1], dB[j * 2 + 1], b1);
            }
            float r2A = hsum2(add2(a0, a1));
            float r2B = hsum2(add2(b0, b1));
            float rA  = r2A * rsqrtf(r2A);
            float rB  = r2B * rsqrtf(r2B);
            float2 ab = s_ab[l * NC + c];           // one LDS.64, warp-broadcast
            float hA  = __fdividef(1.0f, ab.x + rA);
            float hB  = __fdividef(1.0f, ab.x + rB);
            float bhA = ab.y * hA;
            float bhB = ab.y * hB;
            float t1A = 1.0f + bhA;
            float t1B = 1.0f + bhB;
            p15A *= t1A;
            p15B *= t1B;
            pgA  *= fmaf(-bhA, rA * hA, t1A);
            pgB  *= fmaf(-bhB, rB * hB, t1B);
            u64 tA = bcast2(t1A);
            u64 tB = bcast2(t1B);
            ulonglong2 e0 = e2[l * 4 + 0];
            ulonglong2 e1 = e2[l * 4 + 1];
            ulonglong2 e4 = e2[l * 4 + 2];
            ulonglong2 e5 = e2[l * 4 + 3];
            dA[0] = fma2(dA[0], tA, e0.x);  dB[0] = fma2(dB[0], tB, e0.x);
            dA[1] = fma2(dA[1], tA, e0.y);  dB[1] = fma2(dB[1], tB, e0.y);
            dA[2] = fma2(dA[2], tA, e1.x);  dB[2] = fma2(dB[2], tB, e1.x);
            dA[3] = fma2(dA[3], tA, e1.y);  dB[3] = fma2(dB[3], tB, e1.y);
            dA[4] = fma2(dA[4], tA, e4.x);  dB[4] = fma2(dB[4], tB, e4.x);
            dA[5] = fma2(dA[5], tA, e4.y);  dB[5] = fma2(dB[5], tB, e4.y);
            dA[6] = fma2(dA[6], tA, e5.x);  dB[6] = fma2(dB[6], tB, e5.x);
            dA[7] = fma2(dA[7], tA, e5.y);  dB[7] = fma2(dB[7], tB, e5.y);
        }
        float sljA = fmaf(15.0f, __logf(p15A), __logf(pgA));
        float sljB = fmaf(15.0f, __logf(p15B), __logf(pgB));

        // q = |z_K|^2  (mean = 0, P = I)
        u64 a0 = mul2(dA[0], dA[0]);
        u64 a1 = mul2(dA[1], dA[1]);
        u64 b0 = mul2(dB[0], dB[0]);
        u64 b1 = mul2(dB[1], dB[1]);
#pragma unroll
        for (int j = 1; j < 4; j++) {
            a0 = fma2(dA[j * 2 + 0], dA[j * 2 + 0], a0);
            a1 = fma2(dA[j * 2 + 1], dA[j * 2 + 1], a1);
            b0 = fma2(dB[j * 2 + 0], dB[j * 2 + 0], b0);
            b1 = fma2(dB[j * 2 + 1], dB[j * 2 + 1], b1);
        }
        float qA = hsum2(add2(a0, a1));
        float qB = hsum2(add2(b0, b1));

        float base = s_base[c];
        vA = fmaf(qA, -0.5f, base) + sljA;
        vB = fmaf(qB, -0.5f, base) + sljB;
    } else {
        // ================= GENERAL PATH (arbitrary cov/mean) =================
        vA = general_one(z, nnA, c, s_nz0all, s_P, s_nmean, s_ab, s_base);
        vB = general_one(z, nnB, c, s_nz0all, s_P, s_nmean, s_ab, s_base);
    }

    if (isnan(vA)) vA = __int_as_float(0xff800000);
    if (isnan(vB)) vB = __int_as_float(0xff800000);

    // Stage through smem (pitch 17: conflict-free) -> coalesced global stores.
    s_res[lane * 17 + c] = vA;
    s_res[(lane + 32) * 17 + c] = vB;
    __syncthreads();

    const int p  = tid >> 4;            // point 0..31
    const int cm = tid & 15;            // comp  0..15
    const int n2 = blockIdx.x * 64 + p;
    if (n2 < N) out[(size_t)n2 * NC + cm] = s_res[p * 17 + cm];
    const int n3 = n2 + 32;
    if (n3 < N) out[(size_t)n3 * NC + cm] = s_res[(p + 32) * 17 + cm];
}

// ---------------------------------------------------------------------------
// Launch contract
// ---------------------------------------------------------------------------
extern "C" void kernel_launch(void* const* d_in, const int* in_sizes, int n_in,
                              void* d_out, int out_size) {
    const float* z    = (const float*)d_in[0];   // (N, 16)
    const float* z0   = (const float*)d_in[1];   // (6, 16, 16)
    const float* la   = (const float*)d_in[2];   // (6, 16)
    const float* beta = (const float*)d_in[3];   // (6, 16)
    const float* mean = (const float*)d_in[4];   // (16, 16)
    const float* cov  = (const float*)d_in[5];   // (16, 16, 16)
    float* out = (float*)d_out;                  // (N, 16) float32

    const int N = in_sizes[0] / NDIM;

    setup_kernel<<<1, dim3(NDIM, NC)>>>(la, beta, cov, z0, mean);
    const int blocks = (N + 63) / 64;
    density_kernel<<<blocks, 512>>>(z, z0, mean, out, N);
}

// round 9
// speedup vs baseline: 1.0538x; 1.0538x over previous
#include <cuda_runtime.h>
#include <cstdint>
#include <math.h>

#define NC 16       // components
#define NDIM 16     // dimension
#define NL 6        // flow steps
#define PPT 3       // points per thread (fast path)
#define PTS_PER_BLK (32 * PPT)   // 96 points per block

// ---------------------------------------------------------------------------
// Device globals (setup kernel -> main kernel). No dynamic allocation.
// ---------------------------------------------------------------------------
__device__ float g_P[NC * NDIM * NDIM];    // L^{-1} per component (zeros above diag)
__device__ float g_base[NC];               // -0.5*DIM*log(2pi) - half_logdet
__device__ float2 g_ab[NL * NC];           // (exp(log_alpha), beta) packed
__device__ float g_e[NC * NL * NDIM];      // [c][l][i]: l<5: z0_l - z0_{l+1}; l=5: z0_5
__device__ float g_nz00[NC * NDIM];        // -z0_0
__device__ int   g_flag;                   // 1 if P==I for all c and mean==0

// ---------------------------------------------------------------------------
// Packed f32x2 helpers on raw 64-bit pairs.
// ---------------------------------------------------------------------------
typedef unsigned long long u64;

__device__ __forceinline__ u64 add2(u64 a, u64 b) {
    u64 r; asm("add.rn.f32x2 %0, %1, %2;" : "=l"(r) : "l"(a), "l"(b)); return r;
}
__device__ __forceinline__ u64 mul2(u64 a, u64 b) {
    u64 r; asm("mul.rn.f32x2 %0, %1, %2;" : "=l"(r) : "l"(a), "l"(b)); return r;
}
__device__ __forceinline__ u64 fma2(u64 a, u64 b, u64 c) {
    u64 r; asm("fma.rn.f32x2 %0, %1, %2, %3;" : "=l"(r) : "l"(a), "l"(b), "l"(c)); return r;
}
__device__ __forceinline__ u64 bcast2(float x) {
    u64 r; asm("mov.b64 %0, {%1, %1};" : "=l"(r) : "f"(x)); return r;
}
__device__ __forceinline__ u64 pack2(float x, float y) {
    u64 r; asm("mov.b64 %0, {%1, %2};" : "=l"(r) : "f"(x), "f"(y)); return r;
}
__device__ __forceinline__ float hsum2(u64 a) {
    float x, y; asm("mov.b64 {%0, %1}, %2;" : "=f"(x), "=f"(y) : "l"(a));
    return x + y;
}
__device__ __forceinline__ float lo2(u64 a) {
    float x, y; asm("mov.b64 {%0, %1}, %2;" : "=f"(x), "=f"(y) : "l"(a)); return x;
}
__device__ __forceinline__ float hi2(u64 a) {
    float x, y; asm("mov.b64 {%0, %1}, %2;" : "=f"(x), "=f"(y) : "l"(a)); return y;
}

// ---------------------------------------------------------------------------
// Setup: Cholesky -> P = L^{-1}, base, (alpha,beta) pack, flow deltas e,
// and the fast-path flag (P exactly identity AND mean exactly zero).
// One block, (16,16): x = row/element i, y = component c.
// ---------------------------------------------------------------------------
__global__ void setup_kernel(const float* __restrict__ log_alpha,
                             const float* __restrict__ beta_g,
                             const float* __restrict__ cov,
                             const float* __restrict__ z0,
                             const float* __restrict__ mean) {
    const int i = threadIdx.x;   // row / element
    const int c = threadIdx.y;   // component

    __shared__ float scol[NC][NDIM];
    __shared__ float sL[NC][NDIM][NDIM];

    float a[NDIM];
#pragma unroll
    for (int j = 0; j < NDIM; j++) a[j] = cov[(c * NDIM + i) * NDIM + j];

    float Lrow[NDIM];
#pragma unroll
    for (int k = 0; k < NDIM; k++) {
        if (i == k) scol[c][k] = sqrtf(a[k]);
        __syncthreads();
        float lkk = scol[c][k];
        if (i > k) scol[c][i] = a[k] / lkk;
        __syncthreads();
        float lik = (i >= k) ? scol[c][i] : 0.0f;
        Lrow[k] = lik;
        float upd = (i > k) ? lik : 0.0f;
#pragma unroll
        for (int j = 0; j < NDIM; j++) {
            if (j > k) a[j] -= upd * scol[c][j];
        }
        __syncthreads();
    }
#pragma unroll
    for (int k = 0; k < NDIM; k++) sL[c][i][k] = Lrow[k];
    __syncthreads();

    // Thread i computes column i of P = L^{-1} (forward substitution on e_i).
    bool ok = true;
    {
        float x[NDIM];
#pragma unroll
        for (int r = 0; r < NDIM; r++) {
            float s = (r == i) ? 1.0f : 0.0f;
#pragma unroll
            for (int m = 0; m < NDIM; m++) {
                if (m < r) s -= sL[c][r][m] * x[m];
            }
            x[r] = s / sL[c][r][r];
            g_P[(c * NDIM + r) * NDIM + i] = x[r];
            ok = ok && (x[r] == ((r == i) ? 1.0f : 0.0f));
        }
    }
    ok = ok && (mean[c * NDIM + i] == 0.0f);

    if (i == 0) {
        float hld = 0.0f;
#pragma unroll
        for (int d = 0; d < NDIM; d++) hld += logf(sL[c][d][d]);
        g_base[c] = -8.0f * 1.83787706640934548356f - hld;
    }

    // Flow precompute: e[c][l][i]
#pragma unroll
    for (int l = 0; l < NL - 1; l++) {
        g_e[c * (NL * NDIM) + l * NDIM + i] =
            z0[(l * NC + c) * NDIM + i] - z0[((l + 1) * NC + c) * NDIM + i];
    }
    g_e[c * (NL * NDIM) + (NL - 1) * NDIM + i] = z0[((NL - 1) * NC + c) * NDIM + i];
    g_nz00[c * NDIM + i] = -z0[(0 * NC + c) * NDIM + i];

    int t = c * NDIM + i;
    if (t < NL * NC) g_ab[t] = make_float2(expf(log_alpha[t]), beta_g[t]);

    int all = __syncthreads_and(ok ? 1 : 0);
    if (t == 0) g_flag = all;
}

// ---------------------------------------------------------------------------
// General path for one point (arbitrary cov/mean). Correctness-only fallback:
// deliberately register-light (unroll-1 loops, local arrays) so it does not
// inflate the fast path's register allocation.
// ---------------------------------------------------------------------------
__device__ __noinline__ float general_one(const float* __restrict__ z, int nn, int c,
                                          const float* s_nz0all, const float* s_P,
                                          const float* s_nmean, const float2* s_ab,
                                          const float* s_base) {
    float zc[NDIM];
#pragma unroll 1
    for (int j = 0; j < NDIM; j++) zc[j] = z[(size_t)nn * NDIM + j];

    float slj = 0.0f;
#pragma unroll 1
    for (int l = 0; l < NL; l++) {
        float d[NDIM];
        float r2 = 0.0f;
#pragma unroll 1
        for (int j = 0; j < NDIM; j++) {
            float dj = zc[j] + s_nz0all[(l * NC + c) * NDIM + j];
            d[j] = dj;
            r2 = fmaf(dj, dj, r2);
        }
        float r  = sqrtf(r2);
        float2 ab = s_ab[l * NC + c];
        float h  = __fdividef(1.0f, ab.x + r);
        float bh = ab.y * h;
        float rh = r * h;
#pragma unroll 1
        for (int j = 0; j < NDIM; j++) zc[j] = fmaf(d[j], bh, zc[j]);
        float t1 = 1.0f + bh;
        slj = fmaf(15.0f, __logf(t1), slj) + __logf(fmaf(-bh, rh, t1));
    }
#pragma unroll 1
    for (int j = 0; j < NDIM; j++) zc[j] += s_nmean[c * NDIM + j];

    float q = 0.0f;
#pragma unroll 1
    for (int i = 0; i < NDIM; i++) {
        float sol = 0.0f;
#pragma unroll 1
        for (int j = 0; j <= i; j++)
            sol = fmaf(s_P[(c * NDIM + i) * NDIM + j], zc[j], sol);
        q = fmaf(sol, sol, q);
    }
    return fmaf(q, -0.5f, s_base[c]) + slj;
}

// ---------------------------------------------------------------------------
// Main kernel: 512 threads = 16 warps; warp w -> component w.
// Each thread processes THREE points (lane, lane+32, lane+64): amortizes every
// shared broadcast load 3x and gives 3 independent dependency chains.
// ---------------------------------------------------------------------------
__global__ void __launch_bounds__(512, 1)
density_kernel(const float* __restrict__ z,
               const float* __restrict__ z0,
               const float* __restrict__ mean,
               float* __restrict__ out,
               int N)
{
    __shared__ __align__(16) float s_e[NC * NL * NDIM];      // fast-path deltas
    __shared__ __align__(16) float s_nz00[NC * NDIM];        // -z0_0
    __shared__ __align__(16) float s_nz0all[NL * NC * NDIM]; // general path
    __shared__ __align__(16) float s_P[NC * NDIM * NDIM];    // general path
    __shared__ __align__(16) float s_nmean[NC * NDIM];       // general path
    __shared__ float2 s_ab[NL * NC];
    __shared__ float s_base[NC];
    __shared__ float s_res[PTS_PER_BLK * 17];                // [point][comp], pitch 17

    const int tid = threadIdx.x;
    const int flag = g_flag;

    for (int t = tid; t < NC * NL * NDIM; t += 512) s_e[t] = g_e[t];
    if (tid < NC * NDIM) s_nz00[tid] = g_nz00[tid];
    if (tid < NL * NC) s_ab[tid] = g_ab[tid];
    if (tid < NC) s_base[tid] = g_base[tid];
    if (!flag) {
        for (int t = tid; t < NL * NC * NDIM; t += 512) s_nz0all[t] = -z0[t];
        for (int t = tid; t < NC * NDIM * NDIM; t += 512) s_P[t] = g_P[t];
        if (tid < NC * NDIM) s_nmean[tid] = -mean[tid];
    }
    __syncthreads();

    const int c    = tid >> 5;          // warp-uniform component
    const int lane = tid & 31;
    const int base_n = blockIdx.x * PTS_PER_BLK + lane;
    int   npt[PPT];
    int   nn[PPT];
#pragma unroll
    for (int p = 0; p < PPT; p++) {
        npt[p] = base_n + p * 32;
        nn[p]  = (npt[p] < N) ? npt[p] : 0;
    }

    float v[PPT];

    if (flag) {
        // ================= FAST PATH: cov = I, mean = 0 =================
        u64 dA[8], dB[8], dC[8];
        {
            const ulonglong2* zpA = reinterpret_cast<const ulonglong2*>(z + (size_t)nn[0] * NDIM);
            const ulonglong2* zpB = reinterpret_cast<const ulonglong2*>(z + (size_t)nn[1] * NDIM);
            const ulonglong2* zpC = reinterpret_cast<const ulonglong2*>(z + (size_t)nn[2] * NDIM);
            const ulonglong2* z00 = reinterpret_cast<const ulonglong2*>(&s_nz00[c * NDIM]);
#pragma unroll
            for (int q = 0; q < 4; q++) {
                ulonglong2 a = zpA[q];
                ulonglong2 b = zpB[q];
                ulonglong2 cc = zpC[q];
                ulonglong2 m = z00[q];
                dA[q * 2 + 0] = add2(a.x, m.x);
                dA[q * 2 + 1] = add2(a.y, m.y);
                dB[q * 2 + 0] = add2(b.x, m.x);
                dB[q * 2 + 1] = add2(b.y, m.y);
                dC[q * 2 + 0] = add2(cc.x, m.x);
                dC[q * 2 + 1] = add2(cc.y, m.y);
            }
        }

        const ulonglong2* e2 = reinterpret_cast<const ulonglong2*>(&s_e[c * (NL * NDIM)]);
        // packed (p15, pg) log-product accumulators, one per point
        u64 prodA = bcast2(1.0f), prodB = bcast2(1.0f), prodC = bcast2(1.0f);
#pragma unroll
        for (int l = 0; l < NL; l++) {
            // |d|^2 for all three points (independent chains -> ILP)
            u64 a0 = mul2(dA[0], dA[0]);
            u64 a1 = mul2(dA[1], dA[1]);
            u64 b0 = mul2(dB[0], dB[0]);
            u64 b1 = mul2(dB[1], dB[1]);
            u64 c0 = mul2(dC[0], dC[0]);
            u64 c1 = mul2(dC[1], dC[1]);
#pragma unroll
            for (int j = 1; j < 4; j++) {
                a0 = fma2(dA[j * 2 + 0], dA[j * 2 + 0], a0);
                a1 = fma2(dA[j * 2 + 1], dA[j * 2 + 1], a1);
                b0 = fma2(dB[j * 2 + 0], dB[j * 2 + 0], b0);
                b1 = fma2(dB[j * 2 + 1], dB[j * 2 + 1], b1);
                c0 = fma2(dC[j * 2 + 0], dC[j * 2 + 0], c0);
                c1 = fma2(dC[j * 2 + 1], dC[j * 2 + 1], c1);
            }
            float r2A = hsum2(add2(a0, a1));
            float r2B = hsum2(add2(b0, b1));
            float r2C = hsum2(add2(c0, c1));
            float rA  = r2A * rsqrtf(r2A);
            float rB  = r2B * rsqrtf(r2B);
            float rC  = r2C * rsqrtf(r2C);
            float2 ab = s_ab[l * NC + c];           // one LDS.64, warp-broadcast
            float hA  = __fdividef(1.0f, ab.x + rA);
            float hB  = __fdividef(1.0f, ab.x + rB);
            float hC  = __fdividef(1.0f, ab.x + rC);
            float bhA = ab.y * hA;
            float bhB = ab.y * hB;
            float bhC = ab.y * hC;
            float t1A = 1.0f + bhA;
            float t1B = 1.0f + bhB;
            float t1C = 1.0f + bhC;
            prodA = mul2(prodA, pack2(t1A, fmaf(-bhA, rA * hA, t1A)));
            prodB = mul2(prodB, pack2(t1B, fmaf(-bhB, rB * hB, t1B)));
            prodC = mul2(prodC, pack2(t1C, fmaf(-bhC, rC * hC, t1C)));
            u64 tA = bcast2(t1A);
            u64 tB = bcast2(t1B);
            u64 tC = bcast2(t1C);
            ulonglong2 e0 = e2[l * 4 + 0];
            ulonglong2 e1 = e2[l * 4 + 1];
            ulonglong2 e4 = e2[l * 4 + 2];
            ulonglong2 e5 = e2[l * 4 + 3];
            dA[0] = fma2(dA[0], tA, e0.x);  dB[0] = fma2(dB[0], tB, e0.x);  dC[0] = fma2(dC[0], tC, e0.x);
            dA[1] = fma2(dA[1], tA, e0.y);  dB[1] = fma2(dB[1], tB, e0.y);  dC[1] = fma2(dC[1], tC, e0.y);
            dA[2] = fma2(dA[2], tA, e1.x);  dB[2] = fma2(dB[2], tB, e1.x);  dC[2] = fma2(dC[2], tC, e1.x);
            dA[3] = fma2(dA[3], tA, e1.y);  dB[3] = fma2(dB[3], tB, e1.y);  dC[3] = fma2(dC[3], tC, e1.y);
            dA[4] = fma2(dA[4], tA, e4.x);  dB[4] = fma2(dB[4], tB, e4.x);  dC[4] = fma2(dC[4], tC, e4.x);
            dA[5] = fma2(dA[5], tA, e4.y);  dB[5] = fma2(dB[5], tB, e4.y);  dC[5] = fma2(dC[5], tC, e4.y);
            dA[6] = fma2(dA[6], tA, e5.x);  dB[6] = fma2(dB[6], tB, e5.x);  dC[6] = fma2(dC[6], tC, e5.x);
            dA[7] = fma2(dA[7], tA, e5.y);  dB[7] = fma2(dB[7], tB, e5.y);  dC[7] = fma2(dC[7], tC, e5.y);
        }

        // q = |z_K|^2  (mean = 0, P = I)
        u64 a0 = mul2(dA[0], dA[0]);
        u64 a1 = mul2(dA[1], dA[1]);
        u64 b0 = mul2(dB[0], dB[0]);
        u64 b1 = mul2(dB[1], dB[1]);
        u64 c0 = mul2(dC[0], dC[0]);
        u64 c1 = mul2(dC[1], dC[1]);
#pragma unroll
        for (int j = 1; j < 4; j++) {
            a0 = fma2(dA[j * 2 + 0], dA[j * 2 + 0], a0);
            a1 = fma2(dA[j * 2 + 1], dA[j * 2 + 1], a1);
            b0 = fma2(dB[j * 2 + 0], dB[j * 2 + 0], b0);
            b1 = fma2(dB[j * 2 + 1], dB[j * 2 + 1], b1);
            c0 = fma2(dC[j * 2 + 0], dC[j * 2 + 0], c0);
            c1 = fma2(dC[j * 2 + 1], dC[j * 2 + 1], c1);
        }
        float qA = hsum2(add2(a0, a1));
        float qB = hsum2(add2(b0, b1));
        float qC = hsum2(add2(c0, c1));

        float base = s_base[c];
        v[0] = fmaf(qA, -0.5f, base) + fmaf(15.0f, __logf(lo2(prodA)), __logf(hi2(prodA)));
        v[1] = fmaf(qB, -0.5f, base) + fmaf(15.0f, __logf(lo2(prodB)), __logf(hi2(prodB)));
        v[2] = fmaf(qC, -0.5f, base) + fmaf(15.0f, __logf(lo2(prodC)), __logf(hi2(prodC)));
    } else {
        // ================= GENERAL PATH (arbitrary cov/mean) =================
#pragma unroll 1
        for (int p = 0; p < PPT; p++)
            v[p] = general_one(z, nn[p], c, s_nz0all, s_P, s_nmean, s_ab, s_base);
    }

#pragma unroll
    for (int p = 0; p < PPT; p++) {
        float vp = v[p];
        if (isnan(vp)) vp = __int_as_float(0xff800000);   // -inf, matching reference
        s_res[(lane + p * 32) * 17 + c] = vp;
    }
    __syncthreads();

    // Coalesced output: 512 threads cover 96x16 elems in 3 passes.
    const int cm = tid & 15;            // comp 0..15
#pragma unroll
    for (int p = 0; p < PPT; p++) {
        const int pr = (tid >> 4) + p * 32;     // point row 0..95
        const int n2 = blockIdx.x * PTS_PER_BLK + pr;
        if (n2 < N) out[(size_t)n2 * NC + cm] = s_res[pr * 17 + cm];
    }
}

// ---------------------------------------------------------------------------
// Launch contract
// ---------------------------------------------------------------------------
extern "C" void kernel_launch(void* const* d_in, const int* in_sizes, int n_in,
                              void* d_out, int out_size) {
    const float* z    = (const float*)d_in[0];   // (N, 16)
    const float* z0   = (const float*)d_in[1];   // (6, 16, 16)
    const float* la   = (const float*)d_in[2];   // (6, 16)
    const float* beta = (const float*)d_in[3];   // (6, 16)
    const float* mean = (const float*)d_in[4];   // (16, 16)
    const float* cov  = (const float*)d_in[5];   // (16, 16, 16)
    float* out = (float*)d_out;                  // (N, 16) float32

    const int N = in_sizes[0] / NDIM;

    setup_kernel<<<1, dim3(NDIM, NC)>>>(la, beta, cov, z0, mean);
    const int blocks = (N + PTS_PER_BLK - 1) / PTS_PER_BLK;
    density_kernel<<<blocks, 512>>>(z, z0, mean, out, N);
}